// round 16
// baseline (speedup 1.0000x reference)
#include <cuda_runtime.h>
#include <cstdint>

// Problem constants
#define B   16
#define NC  31
#define NO  3
#define NX  256
#define NY  256
#define NLOC 7533          // 3*31*81
#define NGRP 93            // 3*31

// Tiling: one block = (b, o, 8 rows x 256 cols) -- full image width
#define TILE_H 8
#define TILE_W 256
#define THR    128         // 16 thread-cols x 8 thread-rows
#define HALF   128         // lane split: f32x2 lanes are cols (w, w+128)
#define SROWS  16          // TILE_H + 8 halo
#define SP2    136         // float2 pairs per smem row (128 + 8 halo)
#define NCH    68          // 16B chunks per row
#define STILE  (SROWS * SP2)   // 2176 pairs
#define NJ     17              // pairs per staging thread (136/8)

__device__ float2 g_w2[NLOC];  // relu'd weights duplicated into both lanes
__device__ int    g_off[NGRP]; // per (o,c) column offset cx-8 in [-4,4]

__device__ __forceinline__ void fma2(unsigned long long& acc,
                                     unsigned long long a,
                                     unsigned long long b) {
    asm("fma.rn.f32x2 %0, %1, %2, %0;" : "+l"(acc) : "l"(a), "l"(b));
}
__device__ __forceinline__ void unpk2(unsigned long long v, float& lo, float& hi) {
    asm("mov.b64 {%0, %1}, %2;" : "=f"(lo), "=f"(hi) : "l"(v));
}

// chunk permutation: spread 64B-strided thread columns over all bank groups
__device__ __host__ __forceinline__ int swz(int c) {
    return c ^ ((c >> 3) & 7);
}

// 4-byte cp.async with zero-fill (src_size 0 -> zfill)
__device__ __forceinline__ void cpa4(uint32_t dst, const float* src, int sz) {
    asm volatile("cp.async.ca.shared.global [%0], [%1], 4, %2;"
                 :: "r"(dst), "l"(src), "r"(sz));
}
// 8-byte cp.async (weights, always in bounds)
__device__ __forceinline__ void cpa8(uint32_t dst, const float2* src) {
    asm volatile("cp.async.ca.shared.global [%0], [%1], 8;"
                 :: "r"(dst), "l"(src));
}
__device__ __forceinline__ void cpa_commit() {
    asm volatile("cp.async.commit_group;");
}
__device__ __forceinline__ void cpa_wait0() {
    asm volatile("cp.async.wait_group 0;");
}

// ---- prep: relu + duplicate weights, extract per-group column offsets ----
__global__ void prep_kernel(const float* __restrict__ vk,
                            const int* __restrict__ loc) {
    int t = blockIdx.x * blockDim.x + threadIdx.x;
    if (t < NLOC) {
        float w = fmaxf(vk[t], 0.0f);
        g_w2[t] = make_float2(w, w);
    }
    if (t < NGRP) {
        int loc0 = loc[t * 81];          // first entry: (dy=-4, dx=-4)
        g_off[t] = (loc0 % 17) - 4;      // cx - 8
    }
}

// stage channel c's tile + weights into smem via cp.async.
// Row-fixed assignment: thread handles one smem row (tid>>3), 17 pairs along it.
__device__ __forceinline__ void stage_channel(
    const float* __restrict__ x, int b, int o, int c,
    int y0, int tid,
    uint32_t buf_sa, uint32_t wbuf_sa)
{
    const int oc  = g_off[o * NC + c];
    const int gx0 = -4 + oc;                     // x0 == 0 (full-width tile)
    const float* __restrict__ xc = x + ((size_t)(b * NC + c)) * (NX * NY);

    if (tid < 81)
        cpa8(wbuf_sa + tid * 8, &g_w2[(o * NC + c) * 81 + tid]);

    const int row = tid >> 3;                    // 0..15
    const int jp  = tid & 7;                     // pair phase within row
    const int gy  = y0 + row - 4;
    const bool okr = (unsigned)gy < (unsigned)NX;
    const float* rowp = xc + (okr ? gy * NY : 0) + gx0;
    const uint32_t rowdst = buf_sa + row * (SP2 * 8);
    const int pmin  = -gx0;                      // gxa valid iff p >= pmin
    const int pmaxb = 256 - HALF - gx0;          // gxb valid iff p <  pmaxb

    #pragma unroll
    for (int j = 0; j < NJ; j++) {
        int p = jp + 8 * j;                      // 0..135
        int sza = (okr && p >= pmin)  ? 4 : 0;
        int szb = (okr && p <  pmaxb) ? 4 : 0;
        const float* pa = rowp + p;
        const float* pb = pa + HALF;
        uint32_t dst = rowdst + (swz(p >> 1) * 2 + (p & 1)) * 8;
        cpa4(dst,     sza ? pa : rowp - gx0, sza);
        cpa4(dst + 4, szb ? pb : rowp - gx0, szb);
    }
}

// ---- main conv: one block = (b, o, 8x256 tile), cp.async pipelined ----
__global__ __launch_bounds__(THR)
void conv_kernel(const float* __restrict__ x, float* __restrict__ out) {
    __shared__ __align__(16) float2 s2[2][STILE]; // double-buffered tiles
    __shared__ __align__(16) float2 ws[2][81];    // double-buffered weights

    const int bz = blockIdx.z;
    const int b  = bz / NO;
    const int o  = bz % NO;
    const int y0 = blockIdx.y * TILE_H;

    const int tid = threadIdx.x;
    const int twi = tid & 15;        // 0..15 thread-col
    const int thi = tid >> 4;        // 0..7  thread-row (= output row)

    const uint32_t s2_sa = (uint32_t)__cvta_generic_to_shared(&s2[0][0]);
    const uint32_t ws_sa = (uint32_t)__cvta_generic_to_shared(&ws[0][0]);

    // per-thread swizzled chunk byte-offsets within a row (8 chunks)
    int coff[8];
    #pragma unroll
    for (int k = 0; k < 8; k++)
        coff[k] = swz(twi * 4 + k) * 16;

    unsigned long long acc[8];
    #pragma unroll
    for (int j = 0; j < 8; j++) acc[j] = 0ULL;

    // prologue: stage channel 0
    stage_channel(x, b, o, 0, y0, tid, s2_sa, ws_sa);
    cpa_commit();
    cpa_wait0();
    __syncthreads();

    for (int c = 0; c < NC; c++) {
        const int cur = c & 1;
        const int nxt = cur ^ 1;

        // prefetch next channel into the other buffer
        if (c + 1 < NC) {
            stage_channel(x, b, o, c + 1, y0, tid,
                          s2_sa + nxt * (STILE * 8),
                          ws_sa + nxt * (81 * 8));
            cpa_commit();
        }

        const unsigned long long* __restrict__ wsu =
            (const unsigned long long*)ws[cur];
        const float2* __restrict__ sb = s2[cur];

        #pragma unroll
        for (int r = 0; r < 9; r++) {            // 9 input rows, dyi == r
            const char* rb = (const char*)&sb[(thi + r) * SP2];
            unsigned long long q[16];
            #pragma unroll
            for (int k = 0; k < 8; k++) {
                ulonglong2 u = *(const ulonglong2*)(rb + coff[k]);
                q[2 * k]     = u.x;
                q[2 * k + 1] = u.y;
            }

            const unsigned long long* __restrict__ wr = wsu + r * 9;
            #pragma unroll
            for (int dx = 0; dx < 9; dx++) {
                unsigned long long wp = wr[dx];  // LDS.64 broadcast
                #pragma unroll
                for (int j = 0; j < 8; j++)
                    fma2(acc[j], wp, q[dx + j]);
            }
        }

        cpa_wait0();       // next channel's staging has landed
        __syncthreads();   // all warps done reading cur + staging visible
    }

    // write: lane0 -> cols twi*8..twi*8+7, lane1 -> +128
    float* __restrict__ op =
        out + (((size_t)(b * NO + o)) * NX + (y0 + thi)) * NY + twi * 8;
    float lo[8], hi[8];
    #pragma unroll
    for (int j = 0; j < 8; j++) unpk2(acc[j], lo[j], hi[j]);
    *(float4*)(op)            = make_float4(lo[0], lo[1], lo[2], lo[3]);
    *(float4*)(op + 4)        = make_float4(lo[4], lo[5], lo[6], lo[7]);
    *(float4*)(op + HALF)     = make_float4(hi[0], hi[1], hi[2], hi[3]);
    *(float4*)(op + HALF + 4) = make_float4(hi[4], hi[5], hi[6], hi[7]);
}

extern "C" void kernel_launch(void* const* d_in, const int* in_sizes, int n_in,
                              void* d_out, int out_size) {
    const float* x   = (const float*)d_in[0];
    const float* vk  = (const float*)d_in[1];
    const int*   loc = (const int*)d_in[2];
    float* out = (float*)d_out;

    prep_kernel<<<30, 256>>>(vk, loc);

    dim3 grid(1, NX / TILE_H, B * NO);   // (1, 32, 48)
    conv_kernel<<<grid, THR>>>(x, out);
}